// round 7
// baseline (speedup 1.0000x reference)
#include <cuda_runtime.h>
#include <cstdint>

// CBModel: output = concat(gen_poses [2,32,18,256,256], step_poses [2,32,18,256,256]) fp32
//   = 150,994,944 floats = 604 MB, all zeros except <=2304 one-hot elements.
//
// Structure (CUDA-graph fork/join, two concurrent branches):
//   s1 (forked) : fill kernel zeroes the 128-plane TAIL (32 MB) + writes its ones.
//                 Byte-disjoint from the memset region -> runs concurrent from t=0.
//   s0 (capture): cudaMemsetAsync zeroes the 2176-plane HEAD (570 MB, ~7.37 TB/s
//                 driver store path), then a tiny kernel writes the head ones.
//   join        : s0 waits s1 before kernel_launch returns.

static constexpr int BC      = 32 * 18;    // 576
static constexpr int C_KP    = 18;
static constexpr int HW      = 256 * 256;  // 65536 floats per plane
static constexpr int PLANES  = 4 * BC;     // 2304

static constexpr int TAIL_PLANES      = 128;
static constexpr int HEAD_PLANES      = PLANES - TAIL_PLANES;   // 2176
static constexpr int BLOCKS_PER_PLANE = 4;
static constexpr int QUARTER          = HW / BLOCKS_PER_PLANE;  // 16384 floats
static constexpr int FILL_BLOCKS      = TAIL_PLANES * BLOCKS_PER_PLANE; // 512
static constexpr int ONES_BLOCKS      = (HEAD_PLANES + 255) / 256;      // 9

// Hot index for a plane: -1 if out of bounds, else x*256+y.
// Bit-exact to the reference: jnp.trunc+int32 == C trunc cast; floor_divide via
// floorf((b-a)/3); step coords accumulated sequentially (two float roundings).
__device__ __forceinline__ int plane_hot(int plane,
                                         const float* __restrict__ pose1,
                                         const float* __restrict__ pose2)
{
    float cx, cy;
    if (plane < 2 * BC) {
        // gen half: sample-0 coords, replicated over batch
        const int k   = plane / BC;            // 0 -> pose1, 1 -> pose2
        const int rem = plane - k * BC;
        const int c   = rem % C_KP;
        const float* P = k ? pose2 : pose1;
        cx = P[2 * c];
        cy = P[2 * c + 1];
    } else {
        const int q   = plane - 2 * BC;
        const int s   = q / BC;                // 0 -> one step, 1 -> two steps
        const int rem = q - s * BC;            // rem = b*18 + c
        const float ax = pose1[2 * rem],  ay = pose1[2 * rem + 1];
        const float bx = pose2[2 * rem],  by = pose2[2 * rem + 1];
        const float sx = floorf((bx - ax) / 3.0f);
        const float sy = floorf((by - ay) / 3.0f);
        cx = ax + sx;  cy = ay + sy;
        if (s == 1) { cx += sx; cy += sy; }
    }
    const int x = (int)cx;
    const int y = (int)cy;
    const bool valid = (x >= 0) & (x <= 255) & (y >= 0) & (y <= 255);
    return valid ? ((x << 8) | y) : -1;
}

// Tail: zero-fill + ones for planes [HEAD_PLANES, PLANES). 4 blocks per plane.
__global__ __launch_bounds__(256)
void cbmodel_tail_fill_kernel(const float* __restrict__ pose1,
                              const float* __restrict__ pose2,
                              float* __restrict__ out)
{
    const int b     = blockIdx.x;
    const int plane = HEAD_PLANES + (b / BLOCKS_PER_PLANE);
    const int q     = b % BLOCKS_PER_PLANE;
    const int hot   = plane_hot(plane, pose1, pose2);

    float* base = out + (size_t)plane * HW + (size_t)q * QUARTER;
    float4* __restrict__ dst = reinterpret_cast<float4*>(base);
    const float4 z = make_float4(0.0f, 0.0f, 0.0f, 0.0f);
    #pragma unroll
    for (int i = threadIdx.x; i < QUARTER / 4; i += 256) {
        dst[i] = z;
    }

    __syncthreads();
    const int lo = q * QUARTER;
    if (threadIdx.x == 0 && hot >= lo && hot < lo + QUARTER) {
        out[(size_t)plane * HW + hot] = 1.0f;
    }
}

// Head ones: one thread per head plane (runs after the memset).
__global__ __launch_bounds__(256)
void cbmodel_head_ones_kernel(const float* __restrict__ pose1,
                              const float* __restrict__ pose2,
                              float* __restrict__ out)
{
    const int plane = blockIdx.x * 256 + threadIdx.x;
    if (plane < HEAD_PLANES) {
        const int hot = plane_hot(plane, pose1, pose2);
        if (hot >= 0) {
            out[(size_t)plane * HW + hot] = 1.0f;
        }
    }
}

extern "C" void kernel_launch(void* const* d_in, const int* in_sizes, int n_in,
                              void* d_out, int out_size)
{
    const float* pose1 = (const float*)d_in[0];   // [32,18,2] float32
    const float* pose2 = (const float*)d_in[1];   // [32,18,2] float32
    float* out = (float*)d_out;

    (void)in_sizes; (void)n_in; (void)out_size;

    // Host-side resources, created per invocation (kernel_launch runs twice:
    // correctness + capture). No device memory involved; intentionally leaked.
    cudaStream_t s1;
    cudaStreamCreateWithFlags(&s1, cudaStreamNonBlocking);
    cudaEvent_t eFork, eJoin;
    cudaEventCreateWithFlags(&eFork, cudaEventDisableTiming);
    cudaEventCreateWithFlags(&eJoin, cudaEventDisableTiming);

    // Fork: s1 branches off the capture (legacy) stream.
    cudaEventRecord(eFork, 0);
    cudaStreamWaitEvent(s1, eFork, 0);

    // Branch A (s1): tail fill + tail ones, concurrent with the memset.
    cbmodel_tail_fill_kernel<<<FILL_BLOCKS, 256, 0, s1>>>(pose1, pose2, out);

    // Branch B (s0): bulk zero of the head, then head ones.
    cudaMemsetAsync(out, 0, (size_t)HEAD_PLANES * HW * sizeof(float), 0);
    cbmodel_head_ones_kernel<<<ONES_BLOCKS, 256>>>(pose1, pose2, out);

    // Join: capture stream waits for the tail branch.
    cudaEventRecord(eJoin, s1);
    cudaStreamWaitEvent(0, eJoin, 0);
}